// round 8
// baseline (speedup 1.0000x reference)
#include <cuda_runtime.h>
#include <cuda_fp16.h>
#include <cstdint>

// Problem constants (fixed shapes)
#define M_DIM 8192      // B*S
#define N_DIM 4096      // OUT
#define K_DIM 4096      // IN
#define NUM_V 1024      // IN/4
#define LUT_SIZE 256

// Scratch (sanctioned __device__ globals)
__device__ __half g_Xh[(size_t)M_DIM * K_DIM];   // fp16-rounded x      (64 MB)
__device__ __half g_Wh[(size_t)N_DIM * K_DIM];   // reconstructed W[N][K] (32 MB)

// ---------------------------------------------------------------------------
// Kernel 1: merged prep — blocks [0, 16384): reconstruct W; rest: x->fp16
// ---------------------------------------------------------------------------
#define REC_BLOCKS (NUM_V * (N_DIM / 256))        // 16384
#define RX_BLOCKS  ((M_DIM * K_DIM / 4) / 1024)   // 8192
__global__ void prep_kernel(const float4* __restrict__ x,
                            const int* __restrict__ index,
                            const float* __restrict__ luts,
                            const float* __restrict__ scales) {
    const int bid = blockIdx.x;
    const int tid = threadIdx.x;
    if (bid < REC_BLOCKS) {
        int v = bid >> 4;
        int o = (bid & 15) * 256 + tid;

        int i0 = index[(size_t)v * N_DIM + o];
        int i1 = index[((size_t)NUM_V + v) * N_DIM + o];
        float s = scales[(size_t)o * (K_DIM / 128) + (v >> 5)];

        const float4* lut0 = reinterpret_cast<const float4*>(luts) + (size_t)v * LUT_SIZE;
        const float4* lut1 = reinterpret_cast<const float4*>(luts) + ((size_t)NUM_V + v) * LUT_SIZE;
        float4 a = lut0[i0];
        float4 b = lut1[i1];

        __half2 h0 = __float22half2_rn(make_float2((a.x + b.x) * s, (a.y + b.y) * s));
        __half2 h1 = __float22half2_rn(make_float2((a.z + b.z) * s, (a.w + b.w) * s));
        uint2 w;
        w.x = *reinterpret_cast<uint32_t*>(&h0);
        w.y = *reinterpret_cast<uint32_t*>(&h1);
        reinterpret_cast<uint2*>(g_Wh)[(size_t)o * NUM_V + v] = w;
    } else {
        size_t base = (size_t)(bid - REC_BLOCKS) * 1024 + tid;
        #pragma unroll
        for (int it = 0; it < 4; it++) {
            size_t i = base + it * 256;
            float4 v = x[i];
            __half2 h0 = __float22half2_rn(make_float2(v.x, v.y));
            __half2 h1 = __float22half2_rn(make_float2(v.z, v.w));
            uint2 o;
            o.x = *reinterpret_cast<uint32_t*>(&h0);
            o.y = *reinterpret_cast<uint32_t*>(&h1);
            reinterpret_cast<uint2*>(g_Xh)[i] = o;
        }
    }
}

// ---------------------------------------------------------------------------
// Kernel 2: persistent fp16 GEMM, mma.sync m16n8k16 + ldmatrix + continuous
// cross-tile cp.async pipeline (PIPE=3, never drains between tiles).
// C[M,N] = A[M,K] * B[N,K]^T + bias   (fp32 accumulate, fp32 out)
// CTA tile 128x128, 8 warps (2Mx4N), warp tile 64x32, 2 CTAs/SM.
// ---------------------------------------------------------------------------
#define TM 128
#define TN 128
#define BK 64
#define PIPE 3
#define NSTAGE (K_DIM / BK)              // 64
#define NTILES ((M_DIM / TM) * (N_DIM / TN))  // 2048
#define STAGE_A_BYTES (TM * BK * 2)      // 16384
#define STAGE_BYTES (2 * STAGE_A_BYTES)  // 32768 (A then B)
#define SMEM_TOTAL (PIPE * STAGE_BYTES)  // 98304

__device__ __forceinline__ void cp16s(uint32_t sa, const void* g) {
    asm volatile("cp.async.cg.shared.global [%0], [%1], 16;\n" :: "r"(sa), "l"(g));
}

__device__ __forceinline__ void ldsm_x4(uint32_t r[4], uint32_t addr) {
    asm volatile("ldmatrix.sync.aligned.m8n8.x4.shared.b16 {%0,%1,%2,%3}, [%4];"
                 : "=r"(r[0]), "=r"(r[1]), "=r"(r[2]), "=r"(r[3]) : "r"(addr));
}

__device__ __forceinline__ void mma_f16(float c[4], const uint32_t a[4],
                                        uint32_t b0, uint32_t b1) {
    asm volatile(
        "mma.sync.aligned.m16n8k16.row.col.f32.f16.f16.f32 "
        "{%0,%1,%2,%3}, {%4,%5,%6,%7}, {%8,%9}, {%0,%1,%2,%3};\n"
        : "+f"(c[0]), "+f"(c[1]), "+f"(c[2]), "+f"(c[3])
        : "r"(a[0]), "r"(a[1]), "r"(a[2]), "r"(a[3]), "r"(b0), "r"(b1));
}

// raster: groups of 512 tiles = 64 M-tiles x 8 N-tiles
__device__ __forceinline__ void tile_coords(int t, int& mt, int& nt) {
    int gid = t >> 9;
    int rr  = t & 511;
    mt = rr >> 3;
    nt = (gid << 3) + (rr & 7);
}

__global__ __launch_bounds__(256, 2)
void gemm_f16_kernel(const float* __restrict__ bias, float* __restrict__ C) {
    extern __shared__ char smem_raw[];
    const uint32_t smem = (uint32_t)__cvta_generic_to_shared(smem_raw);
    const int tid  = threadIdx.x;
    const int warp = tid >> 5;
    const int lane = tid & 31;
    const int wm   = warp >> 2;   // 0..1 : 64 M rows
    const int wn   = warp & 3;    // 0..3 : 32 N cols
    const int stride = gridDim.x;

    // --- loader geometry ---
    const int lrow = tid >> 3;          // 0..31
    const int lcg  = tid & 7;           // 0..7
    const uint32_t sdst = (uint32_t)(lrow * 128 + ((lcg ^ (lrow & 7)) * 16));
    const size_t lgoffA = (size_t)lrow * K_DIM + lcg * 8;

    // --- fragment geometry (ldmatrix) ---
    const int aRow  = wm * 64 + (lane & 15);
    const int aKsel = lane >> 4;
    const uint32_t aBase = (uint32_t)(aRow * 128);
    const int aXor  = aRow & 7;
    const int nRow  = wn * 32 + (lane & 7) + ((lane >> 4) << 3);
    const int bKsel = (lane >> 3) & 1;
    const uint32_t bBase = (uint32_t)(STAGE_A_BYTES + nRow * 128);
    const int bXor  = nRow & 7;

    // issue one stage (local stage ls of load tile) into buffer lbuf
    #define ISSUE_STAGE(gA, gB, ls, lbuf)                                          \
        {                                                                          \
            const __half* ga = (gA) + (ls) * BK;                                   \
            const __half* gb = (gB) + (ls) * BK;                                   \
            uint32_t sa = smem + (lbuf) * STAGE_BYTES + sdst;                      \
            uint32_t sb = sa + STAGE_A_BYTES;                                      \
            _Pragma("unroll")                                                      \
            for (int i = 0; i < 4; i++) {                                          \
                cp16s(sa + i * (32 * 128), ga + (size_t)i * 32 * K_DIM);           \
                cp16s(sb + i * (32 * 128), gb + (size_t)i * 32 * K_DIM);           \
            }                                                                      \
            asm volatile("cp.async.commit_group;\n" ::);                           \
        }

    float acc[4][4][4];
    #pragma unroll
    for (int i = 0; i < 4; i++)
        #pragma unroll
        for (int j = 0; j < 4; j++)
            #pragma unroll
            for (int r = 0; r < 4; r++) acc[i][j][r] = 0.0f;

    // --- load-side state ---
    int ld_tile = blockIdx.x;
    if (ld_tile >= NTILES) return;
    int mt, nt;
    tile_coords(ld_tile, mt, nt);
    const __half* gA_ld = g_Xh + (size_t)mt * TM * K_DIM + lgoffA;
    const __half* gB_ld = g_Wh + (size_t)nt * TN * K_DIM + lgoffA;
    int ld_ls = 0;      // next local stage to load in ld_tile
    int ld_buf = 0;     // next buffer
    int have_next = 1;

    // prologue: 2 stages
    ISSUE_STAGE(gA_ld, gB_ld, 0, 0);
    ISSUE_STAGE(gA_ld, gB_ld, 1, 1);
    ld_ls = 2; ld_buf = 2;

    int cbuf = 0;       // compute buffer

    for (int tile = blockIdx.x; tile < NTILES; tile += stride) {
        int mtc, ntc;
        tile_coords(tile, mtc, ntc);
        const size_t m0 = (size_t)mtc * TM;
        const size_t n0 = (size_t)ntc * TN;
        const int is_last_tile = (tile + stride >= NTILES);

        for (int kt = 0; kt < NSTAGE; kt++) {
            if (is_last_tile && kt == NSTAGE - 1) {
                asm volatile("cp.async.wait_group 0;\n" ::);
            } else {
                asm volatile("cp.async.wait_group 1;\n" ::);
            }
            __syncthreads();

            // issue next stage (buffer ld_buf was last consumed 3 stages ago,
            // all warps passed that point before the barrier above)
            if (have_next) {
                ISSUE_STAGE(gA_ld, gB_ld, ld_ls, ld_buf);
                ld_buf = (ld_buf + 1) % PIPE;
                if (++ld_ls == NSTAGE) {
                    ld_tile += stride;
                    if (ld_tile < NTILES) {
                        tile_coords(ld_tile, mt, nt);
                        gA_ld = g_Xh + (size_t)mt * TM * K_DIM + lgoffA;
                        gB_ld = g_Wh + (size_t)nt * TN * K_DIM + lgoffA;
                        ld_ls = 0;
                    } else {
                        have_next = 0;
                    }
                }
            }

            const uint32_t sbase = smem + cbuf * STAGE_BYTES;
            cbuf = (cbuf + 1) % PIPE;

            #pragma unroll
            for (int ks = 0; ks < 4; ks++) {
                uint32_t af[4][4];
                #pragma unroll
                for (int mi = 0; mi < 4; mi++) {
                    uint32_t addr = sbase + aBase + mi * (16 * 128)
                                  + (uint32_t)((((ks * 2 + aKsel) ^ aXor)) * 16);
                    ldsm_x4(af[mi], addr);
                }
                uint32_t bf[2][4];
                #pragma unroll
                for (int p = 0; p < 2; p++) {
                    uint32_t addr = sbase + bBase + p * (16 * 128)
                                  + (uint32_t)((((ks * 2 + bKsel) ^ bXor)) * 16);
                    ldsm_x4(bf[p], addr);
                }
                #pragma unroll
                for (int mi = 0; mi < 4; mi++) {
                    #pragma unroll
                    for (int ni = 0; ni < 4; ni++) {
                        mma_f16(acc[mi][ni], af[mi], bf[ni >> 1][(ni & 1) * 2],
                                bf[ni >> 1][(ni & 1) * 2 + 1]);
                    }
                }
            }
        }

        // --- epilogue for this tile (overlaps next tile's in-flight loads) ---
        const int g  = lane >> 2;
        const int t2 = (lane & 3) * 2;
        #pragma unroll
        for (int mi = 0; mi < 4; mi++) {
            size_t m = m0 + wm * 64 + mi * 16 + g;
            float* c0 = C + m * N_DIM;
            float* c1 = C + (m + 8) * N_DIM;
            #pragma unroll
            for (int ni = 0; ni < 4; ni++) {
                size_t n = n0 + wn * 32 + ni * 8 + t2;
                float b0 = bias[n], b1 = bias[n + 1];
                *reinterpret_cast<float2*>(c0 + n) =
                    make_float2(acc[mi][ni][0] + b0, acc[mi][ni][1] + b1);
                *reinterpret_cast<float2*>(c1 + n) =
                    make_float2(acc[mi][ni][2] + b0, acc[mi][ni][3] + b1);
                acc[mi][ni][0] = 0.0f; acc[mi][ni][1] = 0.0f;
                acc[mi][ni][2] = 0.0f; acc[mi][ni][3] = 0.0f;
            }
        }
    }
    #undef ISSUE_STAGE
}

// ---------------------------------------------------------------------------
// Launch
// ---------------------------------------------------------------------------
extern "C" void kernel_launch(void* const* d_in, const int* in_sizes, int n_in,
                              void* d_out, int out_size) {
    const float* x      = (const float*)d_in[0];
    const int*   index  = (const int*)d_in[1];
    const float* luts   = (const float*)d_in[2];
    const float* scales = (const float*)d_in[3];
    const float* bias   = (const float*)d_in[4];
    float* out = (float*)d_out;

    prep_kernel<<<REC_BLOCKS + RX_BLOCKS, 256>>>(
        reinterpret_cast<const float4*>(x), index, luts, scales);

    {
        int nsm = 0;
        cudaDeviceGetAttribute(&nsm, cudaDevAttrMultiProcessorCount, 0);
        if (nsm <= 0) nsm = 148;
        int grid = nsm * 2;
        if (grid > NTILES) grid = NTILES;

        static int attr_set = 0;
        if (!attr_set) {
            cudaFuncSetAttribute(gemm_f16_kernel,
                                 cudaFuncAttributeMaxDynamicSharedMemorySize, SMEM_TOTAL);
            attr_set = 1;
        }
        gemm_f16_kernel<<<grid, 256, SMEM_TOTAL>>>(bias, out);
    }
}

// round 9
// speedup vs baseline: 1.0388x; 1.0388x over previous
#include <cuda_runtime.h>
#include <cuda_fp16.h>
#include <cstdint>

// Problem constants (fixed shapes)
#define M_DIM 8192      // B*S
#define N_DIM 4096      // OUT
#define K_DIM 4096      // IN
#define NUM_V 1024      // IN/4
#define LUT_SIZE 256

// Scratch (sanctioned __device__ globals)
__device__ __half g_Xh[(size_t)M_DIM * K_DIM];   // fp16-rounded x      (64 MB)
__device__ __half g_Wh[(size_t)N_DIM * K_DIM];   // reconstructed W[N][K] (32 MB)

// ---------------------------------------------------------------------------
// Kernel 1: merged prep — blocks [0, 16384): reconstruct W; rest: x->fp16
// ---------------------------------------------------------------------------
#define REC_BLOCKS (NUM_V * (N_DIM / 256))        // 16384
#define RX_BLOCKS  ((M_DIM * K_DIM / 4) / 1024)   // 8192 (256 thr * 4 float4)
__global__ void prep_kernel(const float4* __restrict__ x,
                            const int* __restrict__ index,
                            const float* __restrict__ luts,
                            const float* __restrict__ scales) {
    const int bid = blockIdx.x;
    const int tid = threadIdx.x;
    if (bid < REC_BLOCKS) {
        int v = bid >> 4;
        int o = (bid & 15) * 256 + tid;

        int i0 = index[(size_t)v * N_DIM + o];
        int i1 = index[((size_t)NUM_V + v) * N_DIM + o];
        float s = scales[(size_t)o * (K_DIM / 128) + (v >> 5)];

        const float4* lut0 = reinterpret_cast<const float4*>(luts) + (size_t)v * LUT_SIZE;
        const float4* lut1 = reinterpret_cast<const float4*>(luts) + ((size_t)NUM_V + v) * LUT_SIZE;
        float4 a = lut0[i0];
        float4 b = lut1[i1];

        __half2 h0 = __float22half2_rn(make_float2((a.x + b.x) * s, (a.y + b.y) * s));
        __half2 h1 = __float22half2_rn(make_float2((a.z + b.z) * s, (a.w + b.w) * s));
        uint2 w;
        w.x = *reinterpret_cast<uint32_t*>(&h0);
        w.y = *reinterpret_cast<uint32_t*>(&h1);
        reinterpret_cast<uint2*>(g_Wh)[(size_t)o * NUM_V + v] = w;
    } else {
        // x is read exactly once -> streaming loads keep L2 clean for X/W
        size_t base = (size_t)(bid - REC_BLOCKS) * 1024 + tid;
        #pragma unroll
        for (int it = 0; it < 4; it++) {
            size_t i = base + it * 256;
            float4 v = __ldcs(x + i);
            __half2 h0 = __float22half2_rn(make_float2(v.x, v.y));
            __half2 h1 = __float22half2_rn(make_float2(v.z, v.w));
            uint2 o;
            o.x = *reinterpret_cast<uint32_t*>(&h0);
            o.y = *reinterpret_cast<uint32_t*>(&h1);
            reinterpret_cast<uint2*>(g_Xh)[i] = o;
        }
    }
}

// ---------------------------------------------------------------------------
// Kernel 2: fp16 GEMM, mma.sync m16n8k16 + ldmatrix + cp.async 3-stage pipe
// (R5 configuration — best measured: 602us)
// C[M,N] = A[M,K] * B[N,K]^T + bias   (fp32 accumulate, fp32 out)
// CTA tile 128x128, BK=64 halfs (128B rows, XOR-8 swizzle).
// 8 warps: 2(M) x 4(N), warp tile 64x32.  2 CTAs/SM.  One barrier per stage.
// Epilogue uses streaming stores (C never re-read; keep X/W in L2).
// ---------------------------------------------------------------------------
#define TM 128
#define TN 128
#define BK 64
#define PIPE 3
#define NSTAGE (K_DIM / BK)              // 64
#define STAGE_A_BYTES (TM * BK * 2)      // 16384
#define STAGE_BYTES (2 * STAGE_A_BYTES)  // 32768 (A then B)
#define SMEM_TOTAL (PIPE * STAGE_BYTES)  // 98304

__device__ __forceinline__ void cp16s(uint32_t sa, const void* g) {
    asm volatile("cp.async.cg.shared.global [%0], [%1], 16;\n" :: "r"(sa), "l"(g));
}

__device__ __forceinline__ void ldsm_x4(uint32_t r[4], uint32_t addr) {
    asm volatile("ldmatrix.sync.aligned.m8n8.x4.shared.b16 {%0,%1,%2,%3}, [%4];"
                 : "=r"(r[0]), "=r"(r[1]), "=r"(r[2]), "=r"(r[3]) : "r"(addr));
}

__device__ __forceinline__ void mma_f16(float c[4], const uint32_t a[4],
                                        uint32_t b0, uint32_t b1) {
    asm volatile(
        "mma.sync.aligned.m16n8k16.row.col.f32.f16.f16.f32 "
        "{%0,%1,%2,%3}, {%4,%5,%6,%7}, {%8,%9}, {%0,%1,%2,%3};\n"
        : "+f"(c[0]), "+f"(c[1]), "+f"(c[2]), "+f"(c[3])
        : "r"(a[0]), "r"(a[1]), "r"(a[2]), "r"(a[3]), "r"(b0), "r"(b1));
}

__global__ __launch_bounds__(256, 2)
void gemm_f16_kernel(const float* __restrict__ bias, float* __restrict__ C) {
    extern __shared__ char smem_raw[];
    const uint32_t smem = (uint32_t)__cvta_generic_to_shared(smem_raw);
    const int tid  = threadIdx.x;
    const int warp = tid >> 5;
    const int lane = tid & 31;
    const int wm   = warp >> 2;   // 0..1 : 64 M rows
    const int wn   = warp & 3;    // 0..3 : 32 N cols

    // --- raster: groups of 512 CTAs = 64 M-tiles x 8 N-tiles ---
    const int bid = blockIdx.x;
    const int gid = bid >> 9;
    const int rr  = bid & 511;
    const size_t m0 = (size_t)(rr >> 3) * TM;
    const size_t n0 = (size_t)((gid << 3) + (rr & 7)) * TN;

    // --- loader geometry: thread -> (row = tid>>3, 16B-col = tid&7) ---
    const int lrow = tid >> 3;          // 0..31
    const int lcg  = tid & 7;           // 0..7
    const uint32_t sdst = (uint32_t)(lrow * 128 + ((lcg ^ (lrow & 7)) * 16));
    const __half* gA0 = g_Xh + (m0 + lrow) * K_DIM + lcg * 8;
    const __half* gB0 = g_Wh + (n0 + lrow) * K_DIM + lcg * 8;

    #define LOAD_STAGE(st, buf)                                                   \
        {                                                                         \
            const __half* ga = gA0 + (st) * BK;                                   \
            const __half* gb = gB0 + (st) * BK;                                   \
            uint32_t sa = smem + (buf) * STAGE_BYTES + sdst;                      \
            uint32_t sb = sa + STAGE_A_BYTES;                                     \
            _Pragma("unroll")                                                     \
            for (int i = 0; i < 4; i++) {                                         \
                cp16s(sa + i * (32 * 128), ga + (size_t)i * 32 * K_DIM);          \
                cp16s(sb + i * (32 * 128), gb + (size_t)i * 32 * K_DIM);          \
            }                                                                     \
            asm volatile("cp.async.commit_group;\n" ::);                          \
        }

    // --- fragment-load geometry (ldmatrix) ---
    const int aRow  = wm * 64 + (lane & 15);
    const int aKsel = lane >> 4;                 // 0/1
    const uint32_t aBase = (uint32_t)(aRow * 128);
    const int aXor  = aRow & 7;
    const int nRow  = wn * 32 + (lane & 7) + ((lane >> 4) << 3);
    const int bKsel = (lane >> 3) & 1;
    const uint32_t bBase = (uint32_t)(STAGE_A_BYTES + nRow * 128);
    const int bXor  = nRow & 7;

    float acc[4][4][4];
    #pragma unroll
    for (int i = 0; i < 4; i++)
        #pragma unroll
        for (int j = 0; j < 4; j++)
            #pragma unroll
            for (int r = 0; r < 4; r++) acc[i][j][r] = 0.0f;

    LOAD_STAGE(0, 0);
    LOAD_STAGE(1, 1);

    for (int kt = 0; kt < NSTAGE; kt++) {
        const int buf = kt % PIPE;
        if (kt + 1 < NSTAGE) {
            asm volatile("cp.async.wait_group 1;\n" ::);
        } else {
            asm volatile("cp.async.wait_group 0;\n" ::);
        }
        __syncthreads();

        // prefetch next-next stage BEFORE compute; its buffer ((kt-1)%3) was
        // last read in iteration kt-1, which all warps completed before the
        // barrier above. Single barrier per stage.
        if (kt + 2 < NSTAGE) {
            LOAD_STAGE(kt + 2, (kt + 2) % PIPE);
        }

        const uint32_t sbase = smem + buf * STAGE_BYTES;

        #pragma unroll
        for (int ks = 0; ks < 4; ks++) {
            uint32_t af[4][4];
            #pragma unroll
            for (int mi = 0; mi < 4; mi++) {
                uint32_t addr = sbase + aBase + mi * (16 * 128)
                              + (uint32_t)((((ks * 2 + aKsel) ^ aXor)) * 16);
                ldsm_x4(af[mi], addr);
            }
            uint32_t bf[2][4];
            #pragma unroll
            for (int p = 0; p < 2; p++) {
                uint32_t addr = sbase + bBase + p * (16 * 128)
                              + (uint32_t)((((ks * 2 + bKsel) ^ bXor)) * 16);
                ldsm_x4(bf[p], addr);
            }
            #pragma unroll
            for (int mi = 0; mi < 4; mi++) {
                #pragma unroll
                for (int ni = 0; ni < 4; ni++) {
                    mma_f16(acc[mi][ni], af[mi], bf[ni >> 1][(ni & 1) * 2],
                            bf[ni >> 1][(ni & 1) * 2 + 1]);
                }
            }
        }
    }

    // --- epilogue: + bias, fp32 out, streaming stores ---
    const int g  = lane >> 2;
    const int t2 = (lane & 3) * 2;
    #pragma unroll
    for (int mi = 0; mi < 4; mi++) {
        size_t m = m0 + wm * 64 + mi * 16 + g;
        float* c0 = C + m * N_DIM;
        float* c1 = C + (m + 8) * N_DIM;
        #pragma unroll
        for (int ni = 0; ni < 4; ni++) {
            size_t n = n0 + wn * 32 + ni * 8 + t2;
            float b0 = bias[n], b1 = bias[n + 1];
            __stcs(reinterpret_cast<float2*>(c0 + n),
                   make_float2(acc[mi][ni][0] + b0, acc[mi][ni][1] + b1));
            __stcs(reinterpret_cast<float2*>(c1 + n),
                   make_float2(acc[mi][ni][2] + b0, acc[mi][ni][3] + b1));
        }
    }
    #undef LOAD_STAGE
}

// ---------------------------------------------------------------------------
// Launch
// ---------------------------------------------------------------------------
extern "C" void kernel_launch(void* const* d_in, const int* in_sizes, int n_in,
                              void* d_out, int out_size) {
    const float* x      = (const float*)d_in[0];
    const int*   index  = (const int*)d_in[1];
    const float* luts   = (const float*)d_in[2];
    const float* scales = (const float*)d_in[3];
    const float* bias   = (const float*)d_in[4];
    float* out = (float*)d_out;

    prep_kernel<<<REC_BLOCKS + RX_BLOCKS, 256>>>(
        reinterpret_cast<const float4*>(x), index, luts, scales);

    {
        static int attr_set = 0;
        if (!attr_set) {
            cudaFuncSetAttribute(gemm_f16_kernel,
                                 cudaFuncAttributeMaxDynamicSharedMemorySize, SMEM_TOTAL);
            attr_set = 1;
        }
        dim3 grid((M_DIM / TM) * (N_DIM / TN));  // 2048
        gemm_f16_kernel<<<grid, 256, SMEM_TOTAL>>>(bias, out);
    }
}

// round 10
// speedup vs baseline: 1.0784x; 1.0381x over previous
#include <cuda_runtime.h>
#include <cuda_fp16.h>
#include <cstdint>

// Problem constants (fixed shapes)
#define M_DIM 8192      // B*S
#define N_DIM 4096      // OUT
#define K_DIM 4096      // IN
#define NUM_V 1024      // IN/4
#define LUT_SIZE 256

// Scratch (sanctioned __device__ globals)
__device__ __half g_Xh[(size_t)M_DIM * K_DIM];   // fp16-rounded x      (64 MB)
__device__ __half g_Wh[(size_t)N_DIM * K_DIM];   // reconstructed W[N][K] (32 MB)

// ---------------------------------------------------------------------------
// Kernel 1: merged prep.
//  blocks [0, 2048):   reconstruct W, smem-transposed for coalesced writes
//                      (tile = 32 v x 64 o per block)
//  blocks [2048, ...): x -> fp16 (4 float4 per thread)
// ---------------------------------------------------------------------------
#define REC_BLOCKS 2048                            // 64 o-blocks x 32 v-blocks
#define RX_BLOCKS  ((M_DIM * K_DIM / 4) / 1024)    // 8192
__global__ void prep_kernel(const float4* __restrict__ x,
                            const int* __restrict__ index,
                            const float* __restrict__ luts,
                            const float* __restrict__ scales) {
    __shared__ uint2 smem_t[32][65];   // [v_local][o_local], padded
    const int bid = blockIdx.x;
    const int tid = threadIdx.x;
    if (bid < REC_BLOCKS) {
        const int o0 = (bid & 63) * 64;
        const int v0 = (bid >> 6) * 32;
        const int ol = tid & 63;       // 0..63
        const int vg = tid >> 6;       // 0..3
        const int o  = o0 + ol;

        // v>>5 is constant over the block's 32 v's
        const float s = scales[(size_t)o * (K_DIM / 128) + (v0 >> 5)];

        #pragma unroll
        for (int i = 0; i < 8; i++) {
            const int vl = vg * 8 + i;
            const int v  = v0 + vl;
            int i0 = index[(size_t)v * N_DIM + o];                 // coalesced
            int i1 = index[((size_t)NUM_V + v) * N_DIM + o];       // coalesced

            const float4* lut0 = reinterpret_cast<const float4*>(luts) + (size_t)v * LUT_SIZE;
            const float4* lut1 = reinterpret_cast<const float4*>(luts) + ((size_t)NUM_V + v) * LUT_SIZE;
            float4 a = lut0[i0];
            float4 b = lut1[i1];

            __half2 h0 = __float22half2_rn(make_float2((a.x + b.x) * s, (a.y + b.y) * s));
            __half2 h1 = __float22half2_rn(make_float2((a.z + b.z) * s, (a.w + b.w) * s));
            uint2 w;
            w.x = *reinterpret_cast<uint32_t*>(&h0);
            w.y = *reinterpret_cast<uint32_t*>(&h1);
            smem_t[vl][ol] = w;
        }
        __syncthreads();

        // write phase: warp r-row writes 32 consecutive uint2 -> 256B coalesced
        const int warp = tid >> 5;
        const int lane = tid & 31;
        #pragma unroll
        for (int r = warp; r < 64; r += 8) {
            uint2 w = smem_t[lane][r];
            reinterpret_cast<uint2*>(g_Wh)[(size_t)(o0 + r) * NUM_V + v0 + lane] = w;
        }
    } else {
        // x is read exactly once -> streaming loads keep L2 clean
        size_t base = (size_t)(bid - REC_BLOCKS) * 1024 + tid;
        #pragma unroll
        for (int it = 0; it < 4; it++) {
            size_t i = base + it * 256;
            float4 v = __ldcs(x + i);
            __half2 h0 = __float22half2_rn(make_float2(v.x, v.y));
            __half2 h1 = __float22half2_rn(make_float2(v.z, v.w));
            uint2 o;
            o.x = *reinterpret_cast<uint32_t*>(&h0);
            o.y = *reinterpret_cast<uint32_t*>(&h1);
            reinterpret_cast<uint2*>(g_Xh)[i] = o;
        }
    }
}

// ---------------------------------------------------------------------------
// Kernel 2: fp16 GEMM, mma.sync m16n8k16 + ldmatrix + cp.async 3-stage pipe
// (best measured configuration: ~602-604us)
// C[M,N] = A[M,K] * B[N,K]^T + bias   (fp32 accumulate, fp32 out)
// CTA tile 128x128, BK=64 halfs (128B rows, XOR-8 swizzle).
// 8 warps: 2(M) x 4(N), warp tile 64x32.  2 CTAs/SM.  One barrier per stage.
// ---------------------------------------------------------------------------
#define TM 128
#define TN 128
#define BK 64
#define PIPE 3
#define NSTAGE (K_DIM / BK)              // 64
#define STAGE_A_BYTES (TM * BK * 2)      // 16384
#define STAGE_BYTES (2 * STAGE_A_BYTES)  // 32768 (A then B)
#define SMEM_TOTAL (PIPE * STAGE_BYTES)  // 98304

__device__ __forceinline__ void cp16s(uint32_t sa, const void* g) {
    asm volatile("cp.async.cg.shared.global [%0], [%1], 16;\n" :: "r"(sa), "l"(g));
}

__device__ __forceinline__ void ldsm_x4(uint32_t r[4], uint32_t addr) {
    asm volatile("ldmatrix.sync.aligned.m8n8.x4.shared.b16 {%0,%1,%2,%3}, [%4];"
                 : "=r"(r[0]), "=r"(r[1]), "=r"(r[2]), "=r"(r[3]) : "r"(addr));
}

__device__ __forceinline__ void mma_f16(float c[4], const uint32_t a[4],
                                        uint32_t b0, uint32_t b1) {
    asm volatile(
        "mma.sync.aligned.m16n8k16.row.col.f32.f16.f16.f32 "
        "{%0,%1,%2,%3}, {%4,%5,%6,%7}, {%8,%9}, {%0,%1,%2,%3};\n"
        : "+f"(c[0]), "+f"(c[1]), "+f"(c[2]), "+f"(c[3])
        : "r"(a[0]), "r"(a[1]), "r"(a[2]), "r"(a[3]), "r"(b0), "r"(b1));
}

__global__ __launch_bounds__(256, 2)
void gemm_f16_kernel(const float* __restrict__ bias, float* __restrict__ C) {
    extern __shared__ char smem_raw[];
    const uint32_t smem = (uint32_t)__cvta_generic_to_shared(smem_raw);
    const int tid  = threadIdx.x;
    const int warp = tid >> 5;
    const int lane = tid & 31;
    const int wm   = warp >> 2;   // 0..1 : 64 M rows
    const int wn   = warp & 3;    // 0..3 : 32 N cols

    // --- raster: groups of 512 CTAs = 64 M-tiles x 8 N-tiles ---
    const int bid = blockIdx.x;
    const int gid = bid >> 9;
    const int rr  = bid & 511;
    const size_t m0 = (size_t)(rr >> 3) * TM;
    const size_t n0 = (size_t)((gid << 3) + (rr & 7)) * TN;

    // --- loader geometry: thread -> (row = tid>>3, 16B-col = tid&7) ---
    const int lrow = tid >> 3;          // 0..31
    const int lcg  = tid & 7;           // 0..7
    const uint32_t sdst = (uint32_t)(lrow * 128 + ((lcg ^ (lrow & 7)) * 16));
    const __half* gA0 = g_Xh + (m0 + lrow) * K_DIM + lcg * 8;
    const __half* gB0 = g_Wh + (n0 + lrow) * K_DIM + lcg * 8;

    #define LOAD_STAGE(st, buf)                                                   \
        {                                                                         \
            const __half* ga = gA0 + (st) * BK;                                   \
            const __half* gb = gB0 + (st) * BK;                                   \
            uint32_t sa = smem + (buf) * STAGE_BYTES + sdst;                      \
            uint32_t sb = sa + STAGE_A_BYTES;                                     \
            _Pragma("unroll")                                                     \
            for (int i = 0; i < 4; i++) {                                         \
                cp16s(sa + i * (32 * 128), ga + (size_t)i * 32 * K_DIM);          \
                cp16s(sb + i * (32 * 128), gb + (size_t)i * 32 * K_DIM);          \
            }                                                                     \
            asm volatile("cp.async.commit_group;\n" ::);                          \
        }

    // --- fragment-load geometry (ldmatrix) ---
    const int aRow  = wm * 64 + (lane & 15);
    const int aKsel = lane >> 4;                 // 0/1
    const uint32_t aBase = (uint32_t)(aRow * 128);
    const int aXor  = aRow & 7;
    const int nRow  = wn * 32 + (lane & 7) + ((lane >> 4) << 3);
    const int bKsel = (lane >> 3) & 1;
    const uint32_t bBase = (uint32_t)(STAGE_A_BYTES + nRow * 128);
    const int bXor  = nRow & 7;

    float acc[4][4][4];
    #pragma unroll
    for (int i = 0; i < 4; i++)
        #pragma unroll
        for (int j = 0; j < 4; j++)
            #pragma unroll
            for (int r = 0; r < 4; r++) acc[i][j][r] = 0.0f;

    LOAD_STAGE(0, 0);
    LOAD_STAGE(1, 1);

    for (int kt = 0; kt < NSTAGE; kt++) {
        const int buf = kt % PIPE;
        if (kt + 1 < NSTAGE) {
            asm volatile("cp.async.wait_group 1;\n" ::);
        } else {
            asm volatile("cp.async.wait_group 0;\n" ::);
        }
        __syncthreads();

        // prefetch next-next stage BEFORE compute; its buffer ((kt-1)%3) was
        // last read in iteration kt-1, which all warps completed before the
        // barrier above. Single barrier per stage.
        if (kt + 2 < NSTAGE) {
            LOAD_STAGE(kt + 2, (kt + 2) % PIPE);
        }

        const uint32_t sbase = smem + buf * STAGE_BYTES;

        #pragma unroll
        for (int ks = 0; ks < 4; ks++) {
            uint32_t af[4][4];
            #pragma unroll
            for (int mi = 0; mi < 4; mi++) {
                uint32_t addr = sbase + aBase + mi * (16 * 128)
                              + (uint32_t)((((ks * 2 + aKsel) ^ aXor)) * 16);
                ldsm_x4(af[mi], addr);
            }
            uint32_t bf[2][4];
            #pragma unroll
            for (int p = 0; p < 2; p++) {
                uint32_t addr = sbase + bBase + p * (16 * 128)
                              + (uint32_t)((((ks * 2 + bKsel) ^ bXor)) * 16);
                ldsm_x4(bf[p], addr);
            }
            #pragma unroll
            for (int mi = 0; mi < 4; mi++) {
                #pragma unroll
                for (int ni = 0; ni < 4; ni++) {
                    mma_f16(acc[mi][ni], af[mi], bf[ni >> 1][(ni & 1) * 2],
                            bf[ni >> 1][(ni & 1) * 2 + 1]);
                }
            }
        }
    }

    // --- epilogue: + bias, fp32 out, streaming stores (C never re-read) ---
    const int g  = lane >> 2;
    const int t2 = (lane & 3) * 2;
    #pragma unroll
    for (int mi = 0; mi < 4; mi++) {
        size_t m = m0 + wm * 64 + mi * 16 + g;
        float* c0 = C + m * N_DIM;
        float* c1 = C + (m + 8) * N_DIM;
        #pragma unroll
        for (int ni = 0; ni < 4; ni++) {
            size_t n = n0 + wn * 32 + ni * 8 + t2;
            float b0 = bias[n], b1 = bias[n + 1];
            __stcs(reinterpret_cast<float2*>(c0 + n),
                   make_float2(acc[mi][ni][0] + b0, acc[mi][ni][1] + b1));
            __stcs(reinterpret_cast<float2*>(c1 + n),
                   make_float2(acc[mi][ni][2] + b0, acc[mi][ni][3] + b1));
        }
    }
    #undef LOAD_STAGE
}

// ---------------------------------------------------------------------------
// Launch
// ---------------------------------------------------------------------------
extern "C" void kernel_launch(void* const* d_in, const int* in_sizes, int n_in,
                              void* d_out, int out_size) {
    const float* x      = (const float*)d_in[0];
    const int*   index  = (const int*)d_in[1];
    const float* luts   = (const float*)d_in[2];
    const float* scales = (const float*)d_in[3];
    const float* bias   = (const float*)d_in[4];
    float* out = (float*)d_out;

    prep_kernel<<<REC_BLOCKS + RX_BLOCKS, 256>>>(
        reinterpret_cast<const float4*>(x), index, luts, scales);

    {
        static int attr_set = 0;
        if (!attr_set) {
            cudaFuncSetAttribute(gemm_f16_kernel,
                                 cudaFuncAttributeMaxDynamicSharedMemorySize, SMEM_TOTAL);
            attr_set = 1;
        }
        dim3 grid((M_DIM / TM) * (N_DIM / TN));  // 2048
        gemm_f16_kernel<<<grid, 256, SMEM_TOTAL>>>(bias, out);
    }
}